// round 17
// baseline (speedup 1.0000x reference)
#include <cuda_runtime.h>
#include <cstdint>

// CorrelationLayer1D via single-product TF32 banded GEMM, v9.
// v8 with a 2-slot staging ring (1-chunk lookahead; safe with 1 sync/chunk
// since slot (kk+1)&1's last readers precede sync(kk)) -> smem 47.1KB ->
// 4 CTAs/SM (40 warps). rel_err ~2.9e-4.

#define Cc 256
#define Hh 96
#define Ww 320
#define Dd 41
#define CHW (Hh * Ww)
#define NCH 16
#define PAF 168                    // A staging pitch (floats)
#define SLOT_A 10752               // 16 * 672 B
#define STG_B 21504                // 2 * SLOT_A
#define PBF 200                    // B staging pitch (floats)
#define SLOT_B 12800               // 16 * 800 B
#define SMEMB (STG_B + 2 * SLOT_B) // 47104
#define BP 43

typedef uint32_t u32;

static __device__ __forceinline__ u32 tf32c(float f) {
    u32 r; asm("cvt.rna.tf32.f32 %0,%1;" : "=r"(r) : "f"(f)); return r;
}
static __device__ __forceinline__ void mma_tf32(float* c, const u32* a, const u32* b) {
    asm volatile(
        "mma.sync.aligned.m16n8k8.row.col.f32.tf32.tf32.f32 "
        "{%0,%1,%2,%3},{%4,%5,%6,%7},{%8,%9},{%0,%1,%2,%3};"
        : "+f"(c[0]), "+f"(c[1]), "+f"(c[2]), "+f"(c[3])
        : "r"(a[0]), "r"(a[1]), "r"(a[2]), "r"(a[3]), "r"(b[0]), "r"(b[1]));
}
static __device__ __forceinline__ void cp16(u32 s, const void* g) {
    asm volatile("cp.async.cg.shared.global [%0],[%1],16;" :: "r"(s), "l"(g));
}
static __device__ __forceinline__ void cpcommit() {
    asm volatile("cp.async.commit_group;");
}

__global__ __launch_bounds__(320, 4)
void corr1d_tf32c(const float* __restrict__ x1, const float* __restrict__ x2,
                  float* __restrict__ out) {
    extern __shared__ __align__(16) char sm[];
    const int tid = threadIdx.x, wid = tid >> 5, lid = tid & 31;
    const int g = lid >> 2, tg = lid & 3;
    const int wt = blockIdx.x, h = blockIdx.y, b = blockIdx.z;
    const int W0 = wt * 160;
    const u32 sbase = (u32)__cvta_generic_to_shared(sm);

    const float* X1 = x1 + ((size_t)b * Cc) * CHW + (size_t)h * Ww;
    const float* X2 = x2 + ((size_t)b * Cc) * CHW + (size_t)h * Ww;

    // ---- cp.async tasks (rel offsets within a slot) ----
    const float* gsA[2]; u32 raA[2];
#pragma unroll
    for (int t = 0; t < 2; t++) {
        int idx = tid + 320 * t, c = idx / 40, wq = idx % 40;
        gsA[t] = X1 + (size_t)c * CHW + W0 + 4 * wq;
        raA[t] = (u32)(c * 672 + wq * 16);
    }
    const float* gsB[3]; u32 raB[3]; bool okB[3];
#pragma unroll
    for (int t = 0; t < 3; t++) {
        int idx = tid + 320 * t, c = (idx / 50 < 16) ? idx / 50 : 15, q = idx % 50;
        int w = W0 - 20 + 4 * q;
        okB[t] = (idx < 800) && (w >= 0) && (w + 3 < Ww);
        gsB[t] = X2 + (size_t)c * CHW + (okB[t] ? w : 0);
        raB[t] = (u32)(c * 800 + q * 16);
    }
    // zero static OOB B staging chunks: 2 slots x 16 rows x 5 chunks = 160
    if (tid < 160) {
        int slot = tid / 80, rem = tid % 80, r = rem / 5;
        int qz = rem % 5 + (wt ? 45 : 0);
        *(uint4*)(sm + STG_B + slot * SLOT_B + r * 800 + qz * 16) =
            make_uint4(0, 0, 0, 0);
    }

    const int m0 = wid * 16;

    float acc[7][4];
#pragma unroll
    for (int nt = 0; nt < 7; nt++)
#pragma unroll
        for (int i = 0; i < 4; i++) acc[nt][i] = 0.0f;

    // prologue: chunk 0 -> slot 0
#pragma unroll
    for (int t = 0; t < 2; t++) {
        cp16(sbase + raA[t], gsA[t]);
        gsA[t] += (size_t)16 * CHW;
    }
#pragma unroll
    for (int t = 0; t < 3; t++) {
        if (okB[t]) cp16(sbase + STG_B + raB[t], gsB[t]);
        gsB[t] += (size_t)16 * CHW;
    }
    cpcommit();

#pragma unroll 1
    for (int kk = 0; kk < NCH; kk++) {
        const int slot = kk & 1;
        asm volatile("cp.async.wait_group 0;");
        __syncthreads();   // chunk kk visible; reads of slot kk-1 all done

        // issue chunk kk+1 -> slot slot^1 (last read in compute(kk-1): safe)
        if (kk + 1 < NCH) {
            const u32 bA = sbase + (u32)((slot ^ 1) * SLOT_A);
            const u32 bB = sbase + STG_B + (u32)((slot ^ 1) * SLOT_B);
#pragma unroll
            for (int t = 0; t < 2; t++) {
                cp16(bA + raA[t], gsA[t]);
                gsA[t] += (size_t)16 * CHW;
            }
#pragma unroll
            for (int t = 0; t < 3; t++) {
                if (okB[t]) cp16(bB + raB[t], gsB[t]);
                gsB[t] += (size_t)16 * CHW;
            }
            cpcommit();
        }

        // compute on slot kk&1: fragments straight from fp32 staging
        const float* As = (const float*)(sm + slot * SLOT_A);
        const float* Bs = (const float*)(sm + STG_B + slot * SLOT_B);
#pragma unroll
        for (int ks = 0; ks < 2; ks++) {
            const float* ap = As + (8 * ks + tg) * PAF + m0 + g;
            u32 a[4];
            a[0] = tf32c(ap[0]);
            a[1] = tf32c(ap[8]);
            a[2] = tf32c(ap[4 * PAF]);
            a[3] = tf32c(ap[4 * PAF + 8]);
            const float* bp = Bs + (8 * ks + tg) * PBF + m0 + g;
#pragma unroll
            for (int nt = 0; nt < 7; nt++) {
                u32 bb[2];
                bb[0] = tf32c(bp[8 * nt]);
                bb[1] = tf32c(bp[8 * nt + 4 * PBF]);
                mma_tf32(acc[nt], a, bb);
            }
        }
    }

    __syncthreads();

    // ---- band stage: band[m][d] = D[m][j], d = j - m (m local) ----
    float* band = (float*)sm;
#pragma unroll
    for (int nt = 0; nt < 7; nt++) {
        int jl = 8 * nt + 2 * tg;
        int d0 = jl - g, d2 = jl - g - 8;
        if (d0 >= 0 && d0 < Dd) band[(m0 + g) * BP + d0] = acc[nt][0];
        if (d0 + 1 >= 0 && d0 + 1 < Dd) band[(m0 + g) * BP + d0 + 1] = acc[nt][1];
        if (d2 >= 0 && d2 < Dd) band[(m0 + g + 8) * BP + d2] = acc[nt][2];
        if (d2 + 1 >= 0 && d2 + 1 < Dd) band[(m0 + g + 8) * BP + d2 + 1] = acc[nt][3];
    }
    __syncthreads();

    const int w = tid % 160;
    float* ob = out + ((size_t)b * Dd * Hh + h) * Ww + W0 + w;
#pragma unroll 1
    for (int d = tid / 160; d < Dd; d += 2)
        ob[(size_t)d * Hh * Ww] = band[w * BP + d];
}

extern "C" void kernel_launch(void* const* d_in, const int* in_sizes, int n_in,
                              void* d_out, int out_size) {
    const float* x1 = (const float*)d_in[0];
    const float* x2 = (const float*)d_in[1];
    float* out = (float*)d_out;
    cudaFuncSetAttribute(corr1d_tf32c,
                         cudaFuncAttributeMaxDynamicSharedMemorySize, SMEMB);
    dim3 grid(2, Hh, 8);
    corr1d_tf32c<<<grid, 320, SMEMB>>>(x1, x2, out);
}